// round 14
// baseline (speedup 1.0000x reference)
#include <cuda_runtime.h>
#include <cuda_bf16.h>
#include <cstdint>

#define BB 64
#define TLEN 8192
#define DD 64
#define NSTATE 64
#define NCHUNK 512          // chunks per batch (scan)
#define CLEN 16             // payload transitions per chunk
#define BURN 4              // burn-in steps

#define LOG_2PI 1.8378770664093453f

__device__ __forceinline__ uint32_t smem_u32(const void* p) {
    uint32_t a;
    asm("{ .reg .u64 t; cvta.to.shared.u64 t, %1; cvt.u32.u64 %0, t; }" : "=r"(a) : "l"(p));
    return a;
}

__device__ __forceinline__ uint32_t bfpack(float lo, float hi) {
    __nv_bfloat162 h = __floats2bfloat162_rn(lo, hi);
    uint32_t u;
    memcpy(&u, &h, 4);
    return u;
}

__device__ __forceinline__ float2 bfunpack(uint32_t u) {
    __nv_bfloat162 h;
    memcpy(&h, &u, 4);
    return __bfloat1622float2(h);
}

// ---------------- scratch (static device globals; no allocations) ----------
__device__ __align__(16) __nv_bfloat16 g_pT[(size_t)TLEN * BB * NSTATE + 16384]; // p_T[t][b][n]
__device__ float    g_At[NSTATE * NSTATE];       // staging: g_At[x*64+y] = A[y][x]
__device__ float    g_w1[NSTATE * DD];           // staging [n][d]
__device__ float    g_w2[NSTATE * DD];           // staging [n][d]
__device__ uint32_t g_Bfrag[8][8][32][2];        // emission W fragments [ks][nt][lane][r]
__device__ uint32_t g_Afrag[4][8][32][2];        // scan A fragments     [ks][nt][lane][r]
__device__ float    g_bias[NSTATE];
__device__ float    g_pi[NSTATE];
__device__ float    g_mBpart[4096];
__device__ double   g_chunk[BB * NCHUNK];

// ---------------- K0: prep (256 threads, staged) ----------------------------
__global__ void __launch_bounds__(256) k_prep(const float* __restrict__ tm,
                                              const float* __restrict__ priors,
                                              const float* __restrict__ mu,
                                              const float* __restrict__ lv) {
    const int tid = threadIdx.x;

    // ---- stage A: softmaxes (threads 0..63) ----
    if (tid < 64) {
        int n = tid;
        float row[NSTATE];
        float m = -1e30f;
        #pragma unroll
        for (int j = 0; j < NSTATE; j++) { row[j] = tm[n * NSTATE + j]; m = fmaxf(m, row[j]); }
        float s = 0.f;
        #pragma unroll
        for (int j = 0; j < NSTATE; j++) { row[j] = __expf(row[j] - m); s += row[j]; }
        float inv = 1.0f / s;
        #pragma unroll
        for (int j = 0; j < NSTATE; j++) g_At[j * NSTATE + n] = row[j] * inv;

        float pm = -1e30f;
        #pragma unroll
        for (int j = 0; j < NSTATE; j++) pm = fmaxf(pm, priors[j]);
        float ps = 0.f;
        #pragma unroll
        for (int j = 0; j < NSTATE; j++) ps += __expf(priors[j] - pm);
        g_pi[n] = __expf(priors[n] - pm) / ps;
    }

    // ---- stage B: emission weights, 4 threads per state ----
    {
        const int n  = tid >> 2;
        const int dq = tid & 3;
        float slv = 0.f, smm = 0.f;
        #pragma unroll
        for (int d = dq * 16; d < dq * 16 + 16; d++) {
            float l  = lv[n * DD + d];
            float iv = __expf(-l);
            float mu_ = mu[n * DD + d];
            g_w1[n * DD + d] = mu_ * iv;
            g_w2[n * DD + d] = -0.5f * iv;
            slv += l;
            smm += mu_ * mu_ * iv;
        }
        slv += __shfl_xor_sync(0xffffffffu, slv, 1);
        slv += __shfl_xor_sync(0xffffffffu, slv, 2);
        smm += __shfl_xor_sync(0xffffffffu, smm, 1);
        smm += __shfl_xor_sync(0xffffffffu, smm, 2);
        if (dq == 0)
            g_bias[n] = -0.5f * ((float)DD * LOG_2PI + slv) - 0.5f * smm;
    }
    __syncthreads();   // globals visible CTA-wide

    // ---- stage C: fragment build; thread covers (nt = tid>>5, lane = tid&31) ----
    {
        const int nt   = tid >> 5;
        const int lane = tid & 31;
        const int n    = nt * 8 + (lane >> 2);
        const int tq   = lane & 3;
        const float* w1r = &g_w1[n * DD];
        const float* w2r = &g_w2[n * DD];
        #pragma unroll
        for (int ks = 0; ks < 8; ks++) {
            #pragma unroll
            for (int r = 0; r < 2; r++) {
                int k = ks * 16 + tq * 2 + r * 8;
                float v0 = (k < 64) ? w1r[k] : w2r[k - 64];
                float v1 = (k + 1 < 64) ? w1r[k + 1] : w2r[k + 1 - 64];
                g_Bfrag[ks][nt][lane][r] = bfpack(v0, v1);
            }
        }
        const float* arow = &g_At[n * NSTATE];
        #pragma unroll
        for (int ks = 0; ks < 4; ks++) {
            #pragma unroll
            for (int r = 0; r < 2; r++) {
                int k = ks * 16 + tq * 2 + r * 8;
                g_Afrag[ks][nt][lane][r] = bfpack(arow[k], arow[k + 1]);
            }
        }
    }
}

// ---------------- K1: HMMA emission, low-liveness fragments -----------------
__global__ void __launch_bounds__(128) k_emission(const float* __restrict__ X) {
    __shared__ float s_wred[4];

    const int tid  = threadIdx.x;
    const int wid  = tid >> 5;
    const int lane = tid & 31;
    const int r    = lane >> 2;
    const int c2   = (lane & 3) * 2;
    const int warpbase = wid * 32;
    const size_t tilebase = (size_t)blockIdx.x * 128;

    float acc[2][8][4];
    #pragma unroll
    for (int mt = 0; mt < 2; mt++)
        #pragma unroll
        for (int nt = 0; nt < 8; nt++)
            #pragma unroll
            for (int q = 0; q < 4; q++) acc[mt][nt][q] = 0.f;

    #pragma unroll
    for (int kb = 0; kb < 4; kb++) {
        uint32_t ax[2][4], as[2][4];
        #pragma unroll
        for (int mt = 0; mt < 2; mt++) {
            const float* row0 = X + (tilebase + warpbase + mt * 16 + r) * 64;
            const float* row1 = row0 + 8 * 64;
            float2 p00 = *(const float2*)(row0 + 16 * kb + c2);
            float2 p02 = *(const float2*)(row0 + 16 * kb + c2 + 8);
            float2 p10 = *(const float2*)(row1 + 16 * kb + c2);
            float2 p12 = *(const float2*)(row1 + 16 * kb + c2 + 8);
            ax[mt][0] = bfpack(p00.x, p00.y);
            ax[mt][1] = bfpack(p10.x, p10.y);
            ax[mt][2] = bfpack(p02.x, p02.y);
            ax[mt][3] = bfpack(p12.x, p12.y);
            as[mt][0] = bfpack(p00.x * p00.x, p00.y * p00.y);
            as[mt][1] = bfpack(p10.x * p10.x, p10.y * p10.y);
            as[mt][2] = bfpack(p02.x * p02.x, p02.y * p02.y);
            as[mt][3] = bfpack(p12.x * p12.x, p12.y * p12.y);
        }
        #pragma unroll
        for (int nt = 0; nt < 8; nt++) {
            uint2 bx = *(const uint2*)&g_Bfrag[kb][nt][lane][0];
            uint2 bs = *(const uint2*)&g_Bfrag[kb + 4][nt][lane][0];
            #pragma unroll
            for (int mt = 0; mt < 2; mt++) {
                asm volatile(
                    "mma.sync.aligned.m16n8k16.row.col.f32.bf16.bf16.f32 "
                    "{%0,%1,%2,%3}, {%4,%5,%6,%7}, {%8,%9}, {%0,%1,%2,%3};"
                    : "+f"(acc[mt][nt][0]), "+f"(acc[mt][nt][1]),
                      "+f"(acc[mt][nt][2]), "+f"(acc[mt][nt][3])
                    : "r"(ax[mt][0]), "r"(ax[mt][1]), "r"(ax[mt][2]), "r"(ax[mt][3]),
                      "r"(bx.x), "r"(bx.y));
                asm volatile(
                    "mma.sync.aligned.m16n8k16.row.col.f32.bf16.bf16.f32 "
                    "{%0,%1,%2,%3}, {%4,%5,%6,%7}, {%8,%9}, {%0,%1,%2,%3};"
                    : "+f"(acc[mt][nt][0]), "+f"(acc[mt][nt][1]),
                      "+f"(acc[mt][nt][2]), "+f"(acc[mt][nt][3])
                    : "r"(as[mt][0]), "r"(as[mt][1]), "r"(as[mt][2]), "r"(as[mt][3]),
                      "r"(bs.x), "r"(bs.y));
            }
        }
    }

    float2 bload[8];
    #pragma unroll
    for (int nt = 0; nt < 8; nt++)
        bload[nt] = *(const float2*)&g_bias[nt * 8 + c2];

    float rm[4];
    #pragma unroll
    for (int mt = 0; mt < 2; mt++) {
        float m01 = -1e30f, m23 = -1e30f;
        #pragma unroll
        for (int nt = 0; nt < 8; nt++) {
            acc[mt][nt][0] += bload[nt].x;
            acc[mt][nt][1] += bload[nt].y;
            acc[mt][nt][2] += bload[nt].x;
            acc[mt][nt][3] += bload[nt].y;
            m01 = fmaxf(m01, fmaxf(acc[mt][nt][0], acc[mt][nt][1]));
            m23 = fmaxf(m23, fmaxf(acc[mt][nt][2], acc[mt][nt][3]));
        }
        rm[mt * 2 + 0] = m01;
        rm[mt * 2 + 1] = m23;
    }
    #pragma unroll
    for (int j = 0; j < 4; j++) {
        rm[j] = fmaxf(rm[j], __shfl_xor_sync(0xffffffffu, rm[j], 1));
        rm[j] = fmaxf(rm[j], __shfl_xor_sync(0xffffffffu, rm[j], 2));
    }

    // transposed bf16 store: p_T[t][b][n]
    const int b    = blockIdx.x >> 6;
    const int toff = (blockIdx.x & 63) * 128;
    #pragma unroll
    for (int mt = 0; mt < 2; mt++) {
        #pragma unroll
        for (int dp = 0; dp < 2; dp++) {
            const int rloc = warpbase + r + mt * 16 + dp * 8;
            const size_t t = (size_t)(toff + rloc);
            const float mr = rm[mt * 2 + dp];
            __nv_bfloat16* base = &g_pT[(t * 64 + b) * 64 + c2];
            #pragma unroll
            for (int nt = 0; nt < 8; nt++) {
                float ex = __expf(acc[mt][nt][2 * dp + 0] - mr);
                float ey = __expf(acc[mt][nt][2 * dp + 1] - mr);
                *(uint32_t*)(base + nt * 8) = bfpack(ex, ey);
            }
        }
    }

    float s = ((lane & 3) == 0) ? (rm[0] + rm[1]) + (rm[2] + rm[3]) : 0.f;
    #pragma unroll
    for (int off = 16; off; off >>= 1) s += __shfl_xor_sync(0xffffffffu, s, off);
    if (lane == 0) s_wred[wid] = s;
    __syncthreads();
    if (tid == 0)
        g_mBpart[blockIdx.x] = (s_wred[0] + s_wred[1]) + (s_wred[2] + s_wred[3]);
}

// ---------------- K2: tensor-core GEMM scan --------------------------------
__global__ void __launch_bounds__(128) k_scan2() {
    const int c    = blockIdx.x;
    const int wid  = threadIdx.x >> 5;
    const int lane = threadIdx.x & 31;

    __shared__ __align__(16) __nv_bfloat16 V[64][72];

    uint32_t bfr[4][8][2];
    #pragma unroll
    for (int ks = 0; ks < 4; ks++)
        #pragma unroll
        for (int nt = 0; nt < 8; nt++) {
            uint2 u = *(const uint2*)&g_Afrag[ks][nt][lane][0];
            bfr[ks][nt][0] = u.x; bfr[ks][nt][1] = u.y;
        }

    const int wb   = wid * 16;
    const int row0 = wb + (lane >> 2);
    const int row1 = row0 + 8;
    const int c0   = (lane & 3) * 2;

    const int t0 = (c == 0) ? 1 : (CLEN * c - BURN);
    const int t1 = CLEN * c + CLEN;
    const int tb = (c == 0) ? -1000 : (CLEN * c);

    if (c == 0) {
        #pragma unroll 4
        for (int r = 0; r < 16; r++) {
            int row = wb + r;
            int col = lane * 2;
            float2 pf  = bfunpack(*(const uint32_t*)&g_pT[row * 64 + col]);
            float2 pi2 = *(const float2*)&g_pi[col];
            *(uint32_t*)&V[row][col] = bfpack(pi2.x * pf.x, pi2.y * pf.y);
        }
    } else {
        uint32_t one2 = bfpack(1.f, 1.f);
        #pragma unroll 4
        for (int r = 0; r < 16; r++)
            *(uint32_t*)&V[wb + r][lane * 2] = one2;
    }
    __syncwarp();

    uint32_t pcur[16], pn1[16], pn2[16];
    #pragma unroll
    for (int nt = 0; nt < 8; nt++) {
        size_t ta = (size_t)t0 * 64, tbq = (size_t)(t0 + 1) * 64;
        pcur[2*nt]   = *(const uint32_t*)&g_pT[(ta  + row0) * 64 + nt * 8 + c0];
        pcur[2*nt+1] = *(const uint32_t*)&g_pT[(ta  + row1) * 64 + nt * 8 + c0];
        pn1[2*nt]    = *(const uint32_t*)&g_pT[(tbq + row0) * 64 + nt * 8 + c0];
        pn1[2*nt+1]  = *(const uint32_t*)&g_pT[(tbq + row1) * 64 + nt * 8 + c0];
    }

    double lacc0 = 0.0, lacc1 = 0.0, bnd0 = 0.0, bnd1 = 0.0;
    float msr0 = 1.f, msr1 = 1.f;

    for (int t = t0; t < t1; ++t) {
        const int s = t - t0;
        if (t == tb) {
            bnd0 = (double)logf(msr0) + lacc0;
            bnd1 = (double)logf(msr1) + lacc1;
        }

        float acc[8][4];
        #pragma unroll
        for (int nt = 0; nt < 8; nt++)
            #pragma unroll
            for (int q = 0; q < 4; q++) acc[nt][q] = 0.f;

        #pragma unroll
        for (int ks = 0; ks < 4; ks++) {
            uint32_t a0, a1, a2, a3;
            uint32_t addr = smem_u32(&V[wb + (lane & 15)][ks * 16 + 8 * (lane >> 4)]);
            asm volatile("ldmatrix.sync.aligned.m8n8.x4.shared.b16 {%0,%1,%2,%3}, [%4];"
                         : "=r"(a0), "=r"(a1), "=r"(a2), "=r"(a3) : "r"(addr));
            #pragma unroll
            for (int nt = 0; nt < 8; nt++) {
                asm volatile(
                    "mma.sync.aligned.m16n8k16.row.col.f32.bf16.bf16.f32 "
                    "{%0,%1,%2,%3}, {%4,%5,%6,%7}, {%8,%9}, {%0,%1,%2,%3};"
                    : "+f"(acc[nt][0]), "+f"(acc[nt][1]), "+f"(acc[nt][2]), "+f"(acc[nt][3])
                    : "r"(a0), "r"(a1), "r"(a2), "r"(a3),
                      "r"(bfr[ks][nt][0]), "r"(bfr[ks][nt][1]));
            }
        }

        {
            size_t tq = (size_t)(t + 2) * 64;
            #pragma unroll
            for (int nt = 0; nt < 8; nt++) {
                pn2[2*nt]   = *(const uint32_t*)&g_pT[(tq + row0) * 64 + nt * 8 + c0];
                pn2[2*nt+1] = *(const uint32_t*)&g_pT[(tq + row1) * 64 + nt * 8 + c0];
            }
        }

        float sc0 = 1.f, sc1 = 1.f;
        if (s > 0 && (s & 7) == 0) {
            sc0 = 1.f / msr0; sc1 = 1.f / msr1;
            lacc0 += (double)logf(msr0);
            lacc1 += (double)logf(msr1);
        }

        const bool do_sum = ((s & 7) == 7) || (t == tb - 1) || (t == t1 - 1);
        float sum0 = 0.f, sum1 = 0.f;
        #pragma unroll
        for (int nt = 0; nt < 8; nt++) {
            float2 pa  = bfunpack(pcur[2*nt]);
            float2 pbv = bfunpack(pcur[2*nt+1]);
            float w00 = acc[nt][0] * pa.x  * sc0;
            float w01 = acc[nt][1] * pa.y  * sc0;
            float w10 = acc[nt][2] * pbv.x * sc1;
            float w11 = acc[nt][3] * pbv.y * sc1;
            sum0 += w00 + w01;
            sum1 += w10 + w11;
            *(uint32_t*)&V[row0][nt * 8 + c0] = bfpack(w00, w01);
            *(uint32_t*)&V[row1][nt * 8 + c0] = bfpack(w10, w11);
        }
        if (do_sum) {
            sum0 += __shfl_xor_sync(0xffffffffu, sum0, 1);
            sum0 += __shfl_xor_sync(0xffffffffu, sum0, 2);
            sum1 += __shfl_xor_sync(0xffffffffu, sum1, 1);
            sum1 += __shfl_xor_sync(0xffffffffu, sum1, 2);
            msr0 = sum0;
            msr1 = sum1;
        }

        #pragma unroll
        for (int i = 0; i < 16; i++) { pcur[i] = pn1[i]; pn1[i] = pn2[i]; }
        __syncwarp();
    }

    double end0 = (double)logf(msr0) + lacc0;
    double end1 = (double)logf(msr1) + lacc1;
    if ((lane & 3) == 0) {
        g_chunk[row0 * NCHUNK + c] = end0 - ((c == 0) ? 0.0 : bnd0);
        g_chunk[row1 * NCHUNK + c] = end1 - ((c == 0) ? 0.0 : bnd1);
    }
}

// ---------------- K3: deterministic final sum (1024 threads) ---------------
__global__ void __launch_bounds__(1024) k_final(float* out) {
    __shared__ double part[BB][16];
    __shared__ double tot[BB];
    const int tid = threadIdx.x;
    const int b = tid >> 4, q = tid & 15;
    const int CPQ = NCHUNK / 16;         // 32 chunks per thread

    double s = 0.0;
    #pragma unroll 8
    for (int cc = q * CPQ; cc < q * CPQ + CPQ; cc++) s += g_chunk[b * NCHUNK + cc];
    float ms = 0.f;
    #pragma unroll
    for (int i = q * 4; i < q * 4 + 4; i++) ms += g_mBpart[b * 64 + i];
    part[b][q] = s + (double)ms;
    __syncthreads();
    if (tid < BB) {
        double t = 0.0;
        #pragma unroll
        for (int i = 0; i < 16; i++) t += part[tid][i];
        tot[tid] = t;
    }
    __syncthreads();
    if (tid == 0) {
        double T = 0.0;
        #pragma unroll
        for (int i = 0; i < BB; i++) T += tot[i];
        out[0] = (float)T;
    }
}

// ---------------- launch ---------------------------------------------------
extern "C" void kernel_launch(void* const* d_in, const int* in_sizes, int n_in,
                              void* d_out, int out_size) {
    const float* X   = (const float*)d_in[0];
    const float* tm  = (const float*)d_in[1];
    const float* pri = (const float*)d_in[2];
    const float* mu  = (const float*)d_in[3];
    const float* lv  = (const float*)d_in[4];

    k_prep<<<1, 256>>>(tm, pri, mu, lv);
    k_emission<<<4096, 128>>>(X);
    k_scan2<<<NCHUNK, 128>>>();
    k_final<<<1, 1024>>>((float*)d_out);
}

// round 16
// speedup vs baseline: 1.0587x; 1.0587x over previous
#include <cuda_runtime.h>
#include <cuda_bf16.h>
#include <cstdint>

#define BB 64
#define TLEN 8192
#define DD 64
#define NSTATE 64
#define NCHUNK 512          // chunks per batch (scan)
#define CLEN 16             // payload transitions per chunk
#define BURN 4              // burn-in steps

#define LOG_2PI 1.8378770664093453f

__device__ __forceinline__ uint32_t smem_u32(const void* p) {
    uint32_t a;
    asm("{ .reg .u64 t; cvta.to.shared.u64 t, %1; cvt.u32.u64 %0, t; }" : "=r"(a) : "l"(p));
    return a;
}

__device__ __forceinline__ uint32_t bfpack(float lo, float hi) {
    __nv_bfloat162 h = __floats2bfloat162_rn(lo, hi);
    uint32_t u;
    memcpy(&u, &h, 4);
    return u;
}

__device__ __forceinline__ float2 bfunpack(uint32_t u) {
    __nv_bfloat162 h;
    memcpy(&h, &u, 4);
    return __bfloat1622float2(h);
}

// ---------------- scratch (static device globals; no allocations) ----------
__device__ __align__(16) __nv_bfloat16 g_pT[(size_t)TLEN * BB * NSTATE + 16384]; // p_T[t][b][n]
__device__ float    g_At[NSTATE * NSTATE];       // staging: g_At[x*64+y] = A[y][x]
__device__ float    g_w1[NSTATE * DD];           // staging [n][d]
__device__ float    g_w2[NSTATE * DD];           // staging [n][d]
__device__ uint32_t g_Bfrag[8][8][32][2];        // emission W fragments [ks][nt][lane][r]
__device__ uint32_t g_Afrag[4][8][32][2];        // scan A fragments     [ks][nt][lane][r]
__device__ float    g_bias[NSTATE];
__device__ float    g_pi[NSTATE];
__device__ float    g_mBpart[4096];
__device__ double   g_chunk[BB * NCHUNK];

// ---------------- K0: prep (256 threads, staged) ----------------------------
__global__ void __launch_bounds__(256) k_prep(const float* __restrict__ tm,
                                              const float* __restrict__ priors,
                                              const float* __restrict__ mu,
                                              const float* __restrict__ lv) {
    const int tid = threadIdx.x;

    if (tid < 64) {
        int n = tid;
        float row[NSTATE];
        float m = -1e30f;
        #pragma unroll
        for (int j = 0; j < NSTATE; j++) { row[j] = tm[n * NSTATE + j]; m = fmaxf(m, row[j]); }
        float s = 0.f;
        #pragma unroll
        for (int j = 0; j < NSTATE; j++) { row[j] = __expf(row[j] - m); s += row[j]; }
        float inv = 1.0f / s;
        #pragma unroll
        for (int j = 0; j < NSTATE; j++) g_At[j * NSTATE + n] = row[j] * inv;

        float pm = -1e30f;
        #pragma unroll
        for (int j = 0; j < NSTATE; j++) pm = fmaxf(pm, priors[j]);
        float ps = 0.f;
        #pragma unroll
        for (int j = 0; j < NSTATE; j++) ps += __expf(priors[j] - pm);
        g_pi[n] = __expf(priors[n] - pm) / ps;
    }

    {
        const int n  = tid >> 2;
        const int dq = tid & 3;
        float slv = 0.f, smm = 0.f;
        #pragma unroll
        for (int d = dq * 16; d < dq * 16 + 16; d++) {
            float l  = lv[n * DD + d];
            float iv = __expf(-l);
            float mu_ = mu[n * DD + d];
            g_w1[n * DD + d] = mu_ * iv;
            g_w2[n * DD + d] = -0.5f * iv;
            slv += l;
            smm += mu_ * mu_ * iv;
        }
        slv += __shfl_xor_sync(0xffffffffu, slv, 1);
        slv += __shfl_xor_sync(0xffffffffu, slv, 2);
        smm += __shfl_xor_sync(0xffffffffu, smm, 1);
        smm += __shfl_xor_sync(0xffffffffu, smm, 2);
        if (dq == 0)
            g_bias[n] = -0.5f * ((float)DD * LOG_2PI + slv) - 0.5f * smm;
    }
    __syncthreads();

    {
        const int nt   = tid >> 5;
        const int lane = tid & 31;
        const int n    = nt * 8 + (lane >> 2);
        const int tq   = lane & 3;
        const float* w1r = &g_w1[n * DD];
        const float* w2r = &g_w2[n * DD];
        #pragma unroll
        for (int ks = 0; ks < 8; ks++) {
            #pragma unroll
            for (int r = 0; r < 2; r++) {
                int k = ks * 16 + tq * 2 + r * 8;
                float v0 = (k < 64) ? w1r[k] : w2r[k - 64];
                float v1 = (k + 1 < 64) ? w1r[k + 1] : w2r[k + 1 - 64];
                g_Bfrag[ks][nt][lane][r] = bfpack(v0, v1);
            }
        }
        const float* arow = &g_At[n * NSTATE];
        #pragma unroll
        for (int ks = 0; ks < 4; ks++) {
            #pragma unroll
            for (int r = 0; r < 2; r++) {
                int k = ks * 16 + tq * 2 + r * 8;
                g_Afrag[ks][nt][lane][r] = bfpack(arow[k], arow[k + 1]);
            }
        }
    }
}

// ---------------- K1: HMMA emission, coalesced p write-out ------------------
__global__ void __launch_bounds__(128) k_emission(const float* __restrict__ X) {
    __shared__ __align__(16) __nv_bfloat16 s_p[128][72];   // staged p tile
    __shared__ float s_wred[4];

    const int tid  = threadIdx.x;
    const int wid  = tid >> 5;
    const int lane = tid & 31;
    const int r    = lane >> 2;
    const int c2   = (lane & 3) * 2;
    const int warpbase = wid * 32;
    const size_t tilebase = (size_t)blockIdx.x * 128;

    float acc[2][8][4];
    #pragma unroll
    for (int mt = 0; mt < 2; mt++)
        #pragma unroll
        for (int nt = 0; nt < 8; nt++)
            #pragma unroll
            for (int q = 0; q < 4; q++) acc[mt][nt][q] = 0.f;

    #pragma unroll
    for (int kb = 0; kb < 4; kb++) {
        uint32_t ax[2][4], as[2][4];
        #pragma unroll
        for (int mt = 0; mt < 2; mt++) {
            const float* row0 = X + (tilebase + warpbase + mt * 16 + r) * 64;
            const float* row1 = row0 + 8 * 64;
            float2 p00 = *(const float2*)(row0 + 16 * kb + c2);
            float2 p02 = *(const float2*)(row0 + 16 * kb + c2 + 8);
            float2 p10 = *(const float2*)(row1 + 16 * kb + c2);
            float2 p12 = *(const float2*)(row1 + 16 * kb + c2 + 8);
            ax[mt][0] = bfpack(p00.x, p00.y);
            ax[mt][1] = bfpack(p10.x, p10.y);
            ax[mt][2] = bfpack(p02.x, p02.y);
            ax[mt][3] = bfpack(p12.x, p12.y);
            as[mt][0] = bfpack(p00.x * p00.x, p00.y * p00.y);
            as[mt][1] = bfpack(p10.x * p10.x, p10.y * p10.y);
            as[mt][2] = bfpack(p02.x * p02.x, p02.y * p02.y);
            as[mt][3] = bfpack(p12.x * p12.x, p12.y * p12.y);
        }
        #pragma unroll
        for (int nt = 0; nt < 8; nt++) {
            uint2 bx = *(const uint2*)&g_Bfrag[kb][nt][lane][0];
            uint2 bs = *(const uint2*)&g_Bfrag[kb + 4][nt][lane][0];
            #pragma unroll
            for (int mt = 0; mt < 2; mt++) {
                asm volatile(
                    "mma.sync.aligned.m16n8k16.row.col.f32.bf16.bf16.f32 "
                    "{%0,%1,%2,%3}, {%4,%5,%6,%7}, {%8,%9}, {%0,%1,%2,%3};"
                    : "+f"(acc[mt][nt][0]), "+f"(acc[mt][nt][1]),
                      "+f"(acc[mt][nt][2]), "+f"(acc[mt][nt][3])
                    : "r"(ax[mt][0]), "r"(ax[mt][1]), "r"(ax[mt][2]), "r"(ax[mt][3]),
                      "r"(bx.x), "r"(bx.y));
                asm volatile(
                    "mma.sync.aligned.m16n8k16.row.col.f32.bf16.bf16.f32 "
                    "{%0,%1,%2,%3}, {%4,%5,%6,%7}, {%8,%9}, {%0,%1,%2,%3};"
                    : "+f"(acc[mt][nt][0]), "+f"(acc[mt][nt][1]),
                      "+f"(acc[mt][nt][2]), "+f"(acc[mt][nt][3])
                    : "r"(as[mt][0]), "r"(as[mt][1]), "r"(as[mt][2]), "r"(as[mt][3]),
                      "r"(bs.x), "r"(bs.y));
            }
        }
    }

    float2 bload[8];
    #pragma unroll
    for (int nt = 0; nt < 8; nt++)
        bload[nt] = *(const float2*)&g_bias[nt * 8 + c2];

    float rm[4];
    #pragma unroll
    for (int mt = 0; mt < 2; mt++) {
        float m01 = -1e30f, m23 = -1e30f;
        #pragma unroll
        for (int nt = 0; nt < 8; nt++) {
            acc[mt][nt][0] += bload[nt].x;
            acc[mt][nt][1] += bload[nt].y;
            acc[mt][nt][2] += bload[nt].x;
            acc[mt][nt][3] += bload[nt].y;
            m01 = fmaxf(m01, fmaxf(acc[mt][nt][0], acc[mt][nt][1]));
            m23 = fmaxf(m23, fmaxf(acc[mt][nt][2], acc[mt][nt][3]));
        }
        rm[mt * 2 + 0] = m01;
        rm[mt * 2 + 1] = m23;
    }
    #pragma unroll
    for (int j = 0; j < 4; j++) {
        rm[j] = fmaxf(rm[j], __shfl_xor_sync(0xffffffffu, rm[j], 1));
        rm[j] = fmaxf(rm[j], __shfl_xor_sync(0xffffffffu, rm[j], 2));
    }

    // stage exp(p) into smem (conflict-free scatter), then coalesced write-out
    #pragma unroll
    for (int mt = 0; mt < 2; mt++) {
        #pragma unroll
        for (int dp = 0; dp < 2; dp++) {
            const int rloc = warpbase + r + mt * 16 + dp * 8;
            const float mr = rm[mt * 2 + dp];
            #pragma unroll
            for (int nt = 0; nt < 8; nt++) {
                float ex = __expf(acc[mt][nt][2 * dp + 0] - mr);
                float ey = __expf(acc[mt][nt][2 * dp + 1] - mr);
                *(uint32_t*)&s_p[rloc][nt * 8 + c2] = bfpack(ex, ey);
            }
        }
    }
    __syncthreads();

    const int b    = blockIdx.x >> 6;
    const int toff = (blockIdx.x & 63) * 128;
    #pragma unroll
    for (int q = 0; q < 8; q++) {
        int fid = tid + 128 * q;          // 0..1023 uint4s
        int row = fid >> 3;
        int seg = fid & 7;
        uint4 v = *(const uint4*)&s_p[row][seg * 8];
        *(uint4*)&g_pT[((size_t)(toff + row) * 64 + b) * 64 + seg * 8] = v;
    }

    float s = ((lane & 3) == 0) ? (rm[0] + rm[1]) + (rm[2] + rm[3]) : 0.f;
    #pragma unroll
    for (int off = 16; off; off >>= 1) s += __shfl_xor_sync(0xffffffffu, s, off);
    if (lane == 0) s_wred[wid] = s;
    __syncthreads();
    if (tid == 0)
        g_mBpart[blockIdx.x] = (s_wred[0] + s_wred[1]) + (s_wred[2] + s_wred[3]);
}

// ---------------- K2: tensor-core GEMM scan, coalesced p staging ------------
__global__ void __launch_bounds__(128) k_scan2() {
    const int c    = blockIdx.x;
    const int wid  = threadIdx.x >> 5;
    const int lane = threadIdx.x & 31;

    __shared__ __align__(16) __nv_bfloat16 V[64][72];
    __shared__ __align__(16) __nv_bfloat16 P[4][2][16][72];   // per-warp double buffer

    uint32_t bfr[4][8][2];
    #pragma unroll
    for (int ks = 0; ks < 4; ks++)
        #pragma unroll
        for (int nt = 0; nt < 8; nt++) {
            uint2 u = *(const uint2*)&g_Afrag[ks][nt][lane][0];
            bfr[ks][nt][0] = u.x; bfr[ks][nt][1] = u.y;
        }

    const int wb    = wid * 16;
    const int row0q = lane >> 2;           // 0..7 within slice
    const int row0  = wb + row0q;
    const int row1  = row0 + 8;
    const int c0    = (lane & 3) * 2;

    const int t0 = (c == 0) ? 1 : (CLEN * c - BURN);
    const int t1 = CLEN * c + CLEN;
    const int tb = (c == 0) ? -1000 : (CLEN * c);

    if (c == 0) {
        #pragma unroll 4
        for (int r = 0; r < 16; r++) {
            int row = wb + r;
            int col = lane * 2;
            float2 pf  = bfunpack(*(const uint32_t*)&g_pT[row * 64 + col]);
            float2 pi2 = *(const float2*)&g_pi[col];
            *(uint32_t*)&V[row][col] = bfpack(pi2.x * pf.x, pi2.y * pf.y);
        }
    } else {
        uint32_t one2 = bfpack(1.f, 1.f);
        #pragma unroll 4
        for (int r = 0; r < 16; r++)
            *(uint32_t*)&V[wb + r][lane * 2] = one2;
    }

    // initial slice load for t0 into buffer 0 (coalesced)
    {
        const __nv_bfloat16* src = &g_pT[((size_t)t0 * 64 + wb) * 64];
        #pragma unroll
        for (int j = 0; j < 4; j++) {
            int e = (lane + 32 * j) * 8;
            uint4 v = *(const uint4*)(src + e);
            *(uint4*)&P[wid][0][e >> 6][e & 63] = v;
        }
    }
    __syncwarp();

    double lacc0 = 0.0, lacc1 = 0.0, bnd0 = 0.0, bnd1 = 0.0;
    float msr0 = 1.f, msr1 = 1.f;

    for (int t = t0; t < t1; ++t) {
        const int s   = t - t0;
        const int par = s & 1;
        if (t == tb) {
            bnd0 = (double)logf(msr0) + lacc0;
            bnd1 = (double)logf(msr1) + lacc1;
        }

        float acc[8][4];
        #pragma unroll
        for (int nt = 0; nt < 8; nt++)
            #pragma unroll
            for (int q = 0; q < 4; q++) acc[nt][q] = 0.f;

        #pragma unroll
        for (int ks = 0; ks < 4; ks++) {
            uint32_t a0, a1, a2, a3;
            uint32_t addr = smem_u32(&V[wb + (lane & 15)][ks * 16 + 8 * (lane >> 4)]);
            asm volatile("ldmatrix.sync.aligned.m8n8.x4.shared.b16 {%0,%1,%2,%3}, [%4];"
                         : "=r"(a0), "=r"(a1), "=r"(a2), "=r"(a3) : "r"(addr));
            #pragma unroll
            for (int nt = 0; nt < 8; nt++) {
                asm volatile(
                    "mma.sync.aligned.m16n8k16.row.col.f32.bf16.bf16.f32 "
                    "{%0,%1,%2,%3}, {%4,%5,%6,%7}, {%8,%9}, {%0,%1,%2,%3};"
                    : "+f"(acc[nt][0]), "+f"(acc[nt][1]), "+f"(acc[nt][2]), "+f"(acc[nt][3])
                    : "r"(a0), "r"(a1), "r"(a2), "r"(a3),
                      "r"(bfr[ks][nt][0]), "r"(bfr[ks][nt][1]));
            }
        }

        // coalesced prefetch of slice t+1 into registers (g_pT padded)
        uint4 pf4[4];
        {
            const __nv_bfloat16* src = &g_pT[((size_t)(t + 1) * 64 + wb) * 64];
            #pragma unroll
            for (int j = 0; j < 4; j++)
                pf4[j] = *(const uint4*)(src + (lane + 32 * j) * 8);
        }

        float sc0 = 1.f, sc1 = 1.f;
        if (s > 0 && (s & 7) == 0) {
            sc0 = 1.f / msr0; sc1 = 1.f / msr1;
            lacc0 += (double)logf(msr0);
            lacc1 += (double)logf(msr1);
        }

        const bool do_sum = ((s & 7) == 7) || (t == tb - 1) || (t == t1 - 1);
        float sum0 = 0.f, sum1 = 0.f;
        #pragma unroll
        for (int nt = 0; nt < 8; nt++) {
            float2 pa  = bfunpack(*(const uint32_t*)&P[wid][par][row0q][nt * 8 + c0]);
            float2 pbv = bfunpack(*(const uint32_t*)&P[wid][par][row0q + 8][nt * 8 + c0]);
            float w00 = acc[nt][0] * pa.x  * sc0;
            float w01 = acc[nt][1] * pa.y  * sc0;
            float w10 = acc[nt][2] * pbv.x * sc1;
            float w11 = acc[nt][3] * pbv.y * sc1;
            sum0 += w00 + w01;
            sum1 += w10 + w11;
            *(uint32_t*)&V[row0][nt * 8 + c0] = bfpack(w00, w01);
            *(uint32_t*)&V[row1][nt * 8 + c0] = bfpack(w10, w11);
        }
        if (do_sum) {
            sum0 += __shfl_xor_sync(0xffffffffu, sum0, 1);
            sum0 += __shfl_xor_sync(0xffffffffu, sum0, 2);
            sum1 += __shfl_xor_sync(0xffffffffu, sum1, 1);
            sum1 += __shfl_xor_sync(0xffffffffu, sum1, 2);
            msr0 = sum0;
            msr1 = sum1;
        }

        // stash prefetch into the other buffer
        #pragma unroll
        for (int j = 0; j < 4; j++) {
            int e = (lane + 32 * j) * 8;
            *(uint4*)&P[wid][par ^ 1][e >> 6][e & 63] = pf4[j];
        }
        __syncwarp();
    }

    double end0 = (double)logf(msr0) + lacc0;
    double end1 = (double)logf(msr1) + lacc1;
    if ((lane & 3) == 0) {
        g_chunk[row0 * NCHUNK + c] = end0 - ((c == 0) ? 0.0 : bnd0);
        g_chunk[row1 * NCHUNK + c] = end1 - ((c == 0) ? 0.0 : bnd1);
    }
}

// ---------------- K3: deterministic final sum (pipelined chains) -----------
__global__ void __launch_bounds__(1024) k_final(float* out) {
    __shared__ double part[BB][16];
    __shared__ double tot[BB];
    const int tid = threadIdx.x;
    const int b = tid >> 4, q = tid & 15;
    const int CPQ = NCHUNK / 16;          // 32 chunks per thread

    double s0 = 0.0, s1 = 0.0, s2 = 0.0, s3 = 0.0;
    const double* base = &g_chunk[b * NCHUNK + q * CPQ];
    #pragma unroll
    for (int cc = 0; cc < CPQ; cc += 4) {
        s0 += base[cc];
        s1 += base[cc + 1];
        s2 += base[cc + 2];
        s3 += base[cc + 3];
    }
    float ms = 0.f;
    #pragma unroll
    for (int i = q * 4; i < q * 4 + 4; i++) ms += g_mBpart[b * 64 + i];
    part[b][q] = ((s0 + s1) + (s2 + s3)) + (double)ms;
    __syncthreads();
    if (tid < BB) {
        double t = 0.0;
        #pragma unroll
        for (int i = 0; i < 16; i++) t += part[tid][i];
        tot[tid] = t;
    }
    __syncthreads();
    if (tid == 0) {
        double T = 0.0;
        #pragma unroll
        for (int i = 0; i < BB; i++) T += tot[i];
        out[0] = (float)T;
    }
}

// ---------------- launch ---------------------------------------------------
extern "C" void kernel_launch(void* const* d_in, const int* in_sizes, int n_in,
                              void* d_out, int out_size) {
    const float* X   = (const float*)d_in[0];
    const float* tm  = (const float*)d_in[1];
    const float* pri = (const float*)d_in[2];
    const float* mu  = (const float*)d_in[3];
    const float* lv  = (const float*)d_in[4];

    k_prep<<<1, 256>>>(tm, pri, mu, lv);
    k_emission<<<4096, 128>>>(X);
    k_scan2<<<NCHUNK, 128>>>();
    k_final<<<1, 1024>>>((float*)d_out);
}